// round 9
// baseline (speedup 1.0000x reference)
#include <cuda_runtime.h>
#include <cstdint>

#define NQ     4096
#define NDB    65536
#define DIM    32
#define DAUX   32
#define KNN    5
#define QPB    32            // queries per block
#define PBLK   256           // db points per p-block
#define NBLK   (NDB / PBLK)  // 256
#define THREADS 512
#define BIGF   3.0e38f

// Scratch: db transposed [dim][point]; row 32 holds 0.5*||db||^2.
__device__ float g_dbT[33 * NDB];

// ---------------------------------------------------------------------------
// Prep: tiled transpose of db [65536][32] -> g_dbT [33][65536] (+ half-sq row)
// ---------------------------------------------------------------------------
__global__ void prep_kernel(const float* __restrict__ db) {
    __shared__ float t[32][33];
    const int p0 = blockIdx.x * 32;
    const int tx = threadIdx.x & 31;
    const int ty = threadIdx.x >> 5;     // 0..7

#pragma unroll
    for (int r = 0; r < 4; ++r) {
        int row = ty + r * 8;
        t[tx][row] = db[(p0 + row) * DIM + tx];
    }
    __syncthreads();
#pragma unroll
    for (int r = 0; r < 4; ++r) {
        int d = ty + r * 8;
        g_dbT[d * NDB + p0 + tx] = t[d][tx];
    }
    if (ty == 0) {
        float s = 0.f;
#pragma unroll
        for (int d = 0; d < 32; ++d) { float v = t[d][tx]; s += v * v; }
        g_dbT[32 * NDB + p0 + tx] = 0.5f * s;
    }
}

// ---------------------------------------------------------------------------
// helpers
// ---------------------------------------------------------------------------
__device__ __forceinline__ unsigned long long dup2(float x) {
    unsigned int u = __float_as_uint(x);
    unsigned long long r;
    asm("mov.b64 %0, {%1, %1};" : "=l"(r) : "r"(u));
    return r;
}
__device__ __forceinline__ void fma2(unsigned long long& a,
                                     unsigned long long x, unsigned long long y) {
    asm("fma.rn.f32x2 %0, %1, %2, %0;" : "+l"(a) : "l"(x), "l"(y));
}
__device__ __forceinline__ void unpack2(unsigned long long v, float& lo, float& hi) {
    unsigned int a, b;
    asm("mov.b64 {%0, %1}, %2;" : "=r"(a), "=r"(b) : "l"(v));
    lo = __uint_as_float(a);
    hi = __uint_as_float(b);
}

// sorted-ascending top-5 insert (registers only; rarely-taken branch)
#define TOPK_INS(A, SC, PI) do {                                                        \
    if ((SC) < ts[A][4]) {                                                              \
        ts[A][4] = (SC); ti[A][4] = (PI);                                               \
        if (ts[A][4] < ts[A][3]) { float f_=ts[A][3]; ts[A][3]=ts[A][4]; ts[A][4]=f_;   \
                                   int i_=ti[A][3]; ti[A][3]=ti[A][4]; ti[A][4]=i_; }   \
        if (ts[A][3] < ts[A][2]) { float f_=ts[A][2]; ts[A][2]=ts[A][3]; ts[A][3]=f_;   \
                                   int i_=ti[A][2]; ti[A][2]=ti[A][3]; ti[A][3]=i_; }   \
        if (ts[A][2] < ts[A][1]) { float f_=ts[A][1]; ts[A][1]=ts[A][2]; ts[A][2]=f_;   \
                                   int i_=ti[A][1]; ti[A][1]=ti[A][2]; ti[A][2]=i_; }   \
        if (ts[A][1] < ts[A][0]) { float f_=ts[A][0]; ts[A][0]=ts[A][1]; ts[A][1]=f_;   \
                                   int i_=ti[A][0]; ti[A][0]=ti[A][1]; ti[A][1]=i_; }   \
    } } while (0)

// ---------------------------------------------------------------------------
// Main: 512 threads (16 warps), 32 queries/block. db streamed directly from
// global (L1/L2-resident). Queries pre-duplicated {v,v} in smem so the
// mainloop is 2 LDS.128(bcast) + 1 LDG.128 + 8 FMA2 per d-step — no ALU movs.
// ---------------------------------------------------------------------------
__global__ void __launch_bounds__(THREADS, 1)
knn_kernel(const float* __restrict__ q,
           const float* __restrict__ aux,
           float* __restrict__ out) {
    __shared__ unsigned long long qd[32 * 32];   // [dim][query] dup pairs (8KB)
    __shared__ float cs[QPB * 10];
    __shared__ int   ci[QPB * 10];

    const int tid  = threadIdx.x;
    const int lane = tid & 31;
    const int pg   = tid & 63;             // point group: pg*4 .. +3 within p-block
    const int qg   = tid >> 6;             // query group 0..7: queries qg*4 .. +3
    const int q0   = blockIdx.x * QPB;

    // q tile: duplicated {v,v} pairs, [dim][query] layout
#pragma unroll
    for (int k = 0; k < 2; ++k) {
        int idx = tid + k * THREADS;       // 0..1023
        int row = idx >> 5;                // query
        int col = idx & 31;                // dim
        qd[col * 32 + row] = dup2(q[(q0 + row) * DIM + col]);
    }
    __syncthreads();

    float ts[4][5];
    int   ti[4][5];
#pragma unroll
    for (int a = 0; a < 4; ++a)
#pragma unroll
        for (int b = 0; b < 5; ++b) { ts[a][b] = BIGF; ti[a][b] = 0; }

    for (int b = 0; b < NBLK; ++b) {
        if ((b & 3) == 0) __syncthreads();          // drift control (L1 reuse window)

        const float* pbp = g_dbT + b * PBLK + pg * 4;

        unsigned long long acc[4][2];
#pragma unroll
        for (int a = 0; a < 4; ++a) { acc[a][0] = 0ull; acc[a][1] = 0ull; }

#pragma unroll
        for (int d = 0; d < 32; ++d) {
            // 2x LDS.128 broadcast: 4 pre-duplicated q pairs
            ulonglong2 q01 = *(const ulonglong2*)(qd + d * 32 + qg * 4);
            ulonglong2 q23 = *(const ulonglong2*)(qd + d * 32 + qg * 4 + 2);
            // 1x LDG.128: 4 db points (L1/L2 hit)
            ulonglong2 dv  = *(const ulonglong2*)(pbp + d * NDB);
            fma2(acc[0][0], q01.x, dv.x); fma2(acc[0][1], q01.x, dv.y);
            fma2(acc[1][0], q01.y, dv.x); fma2(acc[1][1], q01.y, dv.y);
            fma2(acc[2][0], q23.x, dv.x); fma2(acc[2][1], q23.x, dv.y);
            fma2(acc[3][0], q23.y, dv.x); fma2(acc[3][1], q23.y, dv.y);
        }

        // score = 0.5||db||^2 - q.db (monotone in distance per query)
        float4 hs = *(const float4*)(g_dbT + 32 * NDB + b * PBLK + pg * 4);
        const int pb = b * PBLK + pg * 4;
#pragma unroll
        for (int a = 0; a < 4; ++a) {
            float v0, v1, v2, v3;
            unpack2(acc[a][0], v0, v1);
            unpack2(acc[a][1], v2, v3);
            float s0 = hs.x - v0, s1 = hs.y - v1, s2 = hs.z - v2, s3 = hs.w - v3;
            TOPK_INS(a, s0, pb + 0);
            TOPK_INS(a, s1, pb + 1);
            TOPK_INS(a, s2, pb + 2);
            TOPK_INS(a, s3, pb + 3);
        }
    }

    // ---- stage 1: per-warp merge (32 lanes) of top-5 lists for 4 queries ----
    const unsigned FULL = 0xffffffffu;
    const int wp = (tid >> 5) & 1;         // which of the 2 warps in this q-group
#pragma unroll
    for (int a = 0; a < 4; ++a) {
        const int ql = qg * 4 + a;         // query within block

        float c0 = ts[a][0], c1 = ts[a][1], c2 = ts[a][2], c3 = ts[a][3], c4 = ts[a][4];
        int   j0 = ti[a][0], j1 = ti[a][1], j2 = ti[a][2], j3 = ti[a][3], j4 = ti[a][4];

#pragma unroll
        for (int k = 0; k < KNN; ++k) {
            float m  = c0;
            int   ml = lane;
#pragma unroll
            for (int off = 16; off; off >>= 1) {
                float om = __shfl_xor_sync(FULL, m, off);
                int   ol = __shfl_xor_sync(FULL, ml, off);
                if (om < m || (om == m && ol < ml)) { m = om; ml = ol; }
            }
            int wi = __shfl_sync(FULL, j0, ml);
            if (lane == k) { cs[ql * 10 + wp * 5 + k] = m; ci[ql * 10 + wp * 5 + k] = wi; }
            if (lane == ml) {
                c0 = c1; c1 = c2; c2 = c3; c3 = c4; c4 = BIGF;
                j0 = j1; j1 = j2; j2 = j3; j3 = j4;
            }
        }
    }
    __syncthreads();

    // ---- stage 2: one warp per 2 queries merges 10 candidates, gathers aux ----
    const int w = tid >> 5;                // 0..15
#pragma unroll
    for (int rq = 0; rq < 2; ++rq) {
        const int ql   = w * 2 + rq;       // 0..31
        const int qidx = q0 + ql;

        float sc = (lane < 10) ? cs[ql * 10 + lane] : BIGF;
        int   id = (lane < 10) ? ci[ql * 10 + lane] : 0;

        // ||q||^2 via warp reduction (lane = dim)
        float qv  = q[qidx * DIM + lane];
        float qsq = qv * qv;
#pragma unroll
        for (int off = 16; off; off >>= 1)
            qsq += __shfl_xor_sync(FULL, qsq, off);

        float wk[KNN]; int bk[KNN];
        float wsum = 0.f;
#pragma unroll
        for (int k = 0; k < KNN; ++k) {
            float m  = sc;
            int   ml = lane;
#pragma unroll
            for (int off = 16; off; off >>= 1) {
                float om = __shfl_xor_sync(FULL, m, off);
                int   ol = __shfl_xor_sync(FULL, ml, off);
                if (om < m || (om == m && ol < ml)) { m = om; ml = ol; }
            }
            int wi = __shfl_sync(FULL, id, ml);
            float dist = sqrtf(fmaxf(qsq + 2.0f * m, 0.0f));
            float wgt  = 1.0f / (dist + 1e-6f);
            wk[k] = wgt; bk[k] = wi; wsum += wgt;
            if (lane == ml) sc = BIGF;     // pop winner
        }

        float acc_o = 0.f;
#pragma unroll
        for (int k = 0; k < KNN; ++k)
            acc_o += wk[k] * aux[bk[k] * DAUX + lane];
        out[qidx * DAUX + lane] = acc_o / wsum;
    }
}

// ---------------------------------------------------------------------------
extern "C" void kernel_launch(void* const* d_in, const int* in_sizes, int n_in,
                              void* d_out, int out_size) {
    const float* q   = (const float*)d_in[0];   // embedding_features [4096,32]
    const float* db  = (const float*)d_in[1];   // db_embedding      [65536,32]
    const float* aux = (const float*)d_in[2];   // auxiliary_features[65536,32]
    float* out = (float*)d_out;                 // [4096,32]

    prep_kernel<<<NDB / 32, 256>>>(db);
    knn_kernel<<<NQ / QPB, THREADS>>>(q, aux, out);
}

// round 10
// speedup vs baseline: 1.2183x; 1.2183x over previous
#include <cuda_runtime.h>
#include <cstdint>

#define NQ     4096
#define NDB    65536
#define DIM    32
#define DAUX   32
#define KNN    5
#define QPB    16            // queries per block
#define PBLK   256           // db points per p-block
#define NBLK   (NDB / PBLK)  // 256
#define THREADS 256
#define BIGF   3.0e38f

// Scratch: db transposed [dim][point]; row 32 holds 0.5*||db||^2.
__device__ float g_dbT[33 * NDB];

// ---------------------------------------------------------------------------
// Prep: tiled transpose of db [65536][32] -> g_dbT [33][65536] (+ half-sq row)
// ---------------------------------------------------------------------------
__global__ void prep_kernel(const float* __restrict__ db) {
    __shared__ float t[32][33];
    const int p0 = blockIdx.x * 32;
    const int tx = threadIdx.x & 31;
    const int ty = threadIdx.x >> 5;     // 0..7

#pragma unroll
    for (int r = 0; r < 4; ++r) {
        int row = ty + r * 8;
        t[tx][row] = db[(p0 + row) * DIM + tx];
    }
    __syncthreads();
#pragma unroll
    for (int r = 0; r < 4; ++r) {
        int d = ty + r * 8;
        g_dbT[d * NDB + p0 + tx] = t[d][tx];
    }
    if (ty == 0) {
        float s = 0.f;
#pragma unroll
        for (int d = 0; d < 32; ++d) { float v = t[d][tx]; s += v * v; }
        g_dbT[32 * NDB + p0 + tx] = 0.5f * s;
    }
}

// ---------------------------------------------------------------------------
// helpers
// ---------------------------------------------------------------------------
__device__ __forceinline__ unsigned long long dup2(float x) {
    unsigned int u = __float_as_uint(x);
    unsigned long long r;
    asm("mov.b64 %0, {%1, %1};" : "=l"(r) : "r"(u));
    return r;
}
__device__ __forceinline__ void fma2(unsigned long long& a,
                                     unsigned long long x, unsigned long long y) {
    asm("fma.rn.f32x2 %0, %1, %2, %0;" : "+l"(a) : "l"(x), "l"(y));
}
__device__ __forceinline__ void unpack2(unsigned long long v, float& lo, float& hi) {
    unsigned int a, b;
    asm("mov.b64 {%0, %1}, %2;" : "=r"(a), "=r"(b) : "l"(v));
    lo = __uint_as_float(a);
    hi = __uint_as_float(b);
}

// sorted-ascending top-5 insert (registers only; rarely-taken branch)
#define TOPK_INS(A, SC, PI) do {                                                        \
    if ((SC) < ts[A][4]) {                                                              \
        ts[A][4] = (SC); ti[A][4] = (PI);                                               \
        if (ts[A][4] < ts[A][3]) { float f_=ts[A][3]; ts[A][3]=ts[A][4]; ts[A][4]=f_;   \
                                   int i_=ti[A][3]; ti[A][3]=ti[A][4]; ti[A][4]=i_; }   \
        if (ts[A][3] < ts[A][2]) { float f_=ts[A][2]; ts[A][2]=ts[A][3]; ts[A][3]=f_;   \
                                   int i_=ti[A][2]; ti[A][2]=ti[A][3]; ti[A][3]=i_; }   \
        if (ts[A][2] < ts[A][1]) { float f_=ts[A][1]; ts[A][1]=ts[A][2]; ts[A][2]=f_;   \
                                   int i_=ti[A][1]; ti[A][1]=ti[A][2]; ti[A][2]=i_; }   \
        if (ts[A][1] < ts[A][0]) { float f_=ts[A][0]; ts[A][0]=ts[A][1]; ts[A][1]=f_;   \
                                   int i_=ti[A][0]; ti[A][0]=ti[A][1]; ti[A][1]=i_; }   \
    } } while (0)

// ---------------------------------------------------------------------------
// Main: 256 threads, 16 queries/block, 2 CTAs co-resident per SM
// (128 regs/thread x 512 threads = full RF). db streamed directly from
// global (L1/L2-resident). Per-thread 4q x 4p f32x2 micro-tile — the R7
// instruction mix, unchanged.
// ---------------------------------------------------------------------------
__global__ void __launch_bounds__(THREADS, 2)
knn_kernel(const float* __restrict__ q,
           const float* __restrict__ aux,
           float* __restrict__ out) {
    __shared__ float q_t[32][QPB];         // [dim][query]
    __shared__ float cs[QPB * 10];
    __shared__ int   ci[QPB * 10];

    const int tid  = threadIdx.x;
    const int lane = tid & 31;
    const int pg   = tid & 63;             // point group: pg*4 .. +3 within p-block
    const int qg   = tid >> 6;             // query group 0..3: queries qg*4 .. +3
    const int q0   = blockIdx.x * QPB;

    // q tile transposed into smem [d][q]  (16 q * 32 d = 512 elems)
#pragma unroll
    for (int k = 0; k < 2; ++k) {
        int idx = tid + k * THREADS;       // 0..511
        int row = idx >> 5;                // query (0..15)
        int col = idx & 31;                // dim
        q_t[col][row] = q[(q0 + row) * DIM + col];
    }
    __syncthreads();

    float ts[4][5];
    int   ti[4][5];
#pragma unroll
    for (int a = 0; a < 4; ++a)
#pragma unroll
        for (int b = 0; b < 5; ++b) { ts[a][b] = BIGF; ti[a][b] = 0; }

    for (int b = 0; b < NBLK; ++b) {
        if ((b & 3) == 0) __syncthreads();          // drift control (L1 reuse window)

        const float* pbp = g_dbT + b * PBLK + pg * 4;

        unsigned long long acc[4][2];
#pragma unroll
        for (int a = 0; a < 4; ++a) { acc[a][0] = 0ull; acc[a][1] = 0ull; }

#pragma unroll
        for (int d = 0; d < 32; ++d) {
            float4 qv = *(const float4*)&q_t[d][qg * 4];   // LDS broadcast
            unsigned long long qa = dup2(qv.x);
            unsigned long long qb = dup2(qv.y);
            unsigned long long qc = dup2(qv.z);
            unsigned long long qd = dup2(qv.w);
            ulonglong2 dv = *(const ulonglong2*)(pbp + d * NDB);   // LDG.128 (L1/L2 hit)
            fma2(acc[0][0], qa, dv.x); fma2(acc[0][1], qa, dv.y);
            fma2(acc[1][0], qb, dv.x); fma2(acc[1][1], qb, dv.y);
            fma2(acc[2][0], qc, dv.x); fma2(acc[2][1], qc, dv.y);
            fma2(acc[3][0], qd, dv.x); fma2(acc[3][1], qd, dv.y);
        }

        // score = 0.5||db||^2 - q.db (monotone in distance per query)
        float4 hs = *(const float4*)(g_dbT + 32 * NDB + b * PBLK + pg * 4);
        const int pb = b * PBLK + pg * 4;
#pragma unroll
        for (int a = 0; a < 4; ++a) {
            float v0, v1, v2, v3;
            unpack2(acc[a][0], v0, v1);
            unpack2(acc[a][1], v2, v3);
            float s0 = hs.x - v0, s1 = hs.y - v1, s2 = hs.z - v2, s3 = hs.w - v3;
            TOPK_INS(a, s0, pb + 0);
            TOPK_INS(a, s1, pb + 1);
            TOPK_INS(a, s2, pb + 2);
            TOPK_INS(a, s3, pb + 3);
        }
    }

    // ---- stage 1: per-warp merge (32 lanes) of top-5 lists for 4 queries ----
    const unsigned FULL = 0xffffffffu;
    const int wp = (tid >> 5) & 1;         // which of the 2 warps in this q-group
#pragma unroll
    for (int a = 0; a < 4; ++a) {
        const int ql = qg * 4 + a;         // query within block (0..15)

        float c0 = ts[a][0], c1 = ts[a][1], c2 = ts[a][2], c3 = ts[a][3], c4 = ts[a][4];
        int   j0 = ti[a][0], j1 = ti[a][1], j2 = ti[a][2], j3 = ti[a][3], j4 = ti[a][4];

#pragma unroll
        for (int k = 0; k < KNN; ++k) {
            float m  = c0;
            int   ml = lane;
#pragma unroll
            for (int off = 16; off; off >>= 1) {
                float om = __shfl_xor_sync(FULL, m, off);
                int   ol = __shfl_xor_sync(FULL, ml, off);
                if (om < m || (om == m && ol < ml)) { m = om; ml = ol; }
            }
            int wi = __shfl_sync(FULL, j0, ml);
            if (lane == k) { cs[ql * 10 + wp * 5 + k] = m; ci[ql * 10 + wp * 5 + k] = wi; }
            if (lane == ml) {
                c0 = c1; c1 = c2; c2 = c3; c3 = c4; c4 = BIGF;
                j0 = j1; j1 = j2; j2 = j3; j3 = j4;
            }
        }
    }
    __syncthreads();

    // ---- stage 2: one warp per 2 queries merges 10 candidates, gathers aux ----
    const int w = tid >> 5;                // 0..7
#pragma unroll
    for (int rq = 0; rq < 2; ++rq) {
        const int ql   = w * 2 + rq;       // 0..15
        const int qidx = q0 + ql;

        float sc = (lane < 10) ? cs[ql * 10 + lane] : BIGF;
        int   id = (lane < 10) ? ci[ql * 10 + lane] : 0;

        // ||q||^2 via warp reduction (lane = dim)
        float qv  = q[qidx * DIM + lane];
        float qsq = qv * qv;
#pragma unroll
        for (int off = 16; off; off >>= 1)
            qsq += __shfl_xor_sync(FULL, qsq, off);

        float wk[KNN]; int bk[KNN];
        float wsum = 0.f;
#pragma unroll
        for (int k = 0; k < KNN; ++k) {
            float m  = sc;
            int   ml = lane;
#pragma unroll
            for (int off = 16; off; off >>= 1) {
                float om = __shfl_xor_sync(FULL, m, off);
                int   ol = __shfl_xor_sync(FULL, ml, off);
                if (om < m || (om == m && ol < ml)) { m = om; ml = ol; }
            }
            int wi = __shfl_sync(FULL, id, ml);
            float dist = sqrtf(fmaxf(qsq + 2.0f * m, 0.0f));
            float wgt  = 1.0f / (dist + 1e-6f);
            wk[k] = wgt; bk[k] = wi; wsum += wgt;
            if (lane == ml) sc = BIGF;     // pop winner
        }

        float acc_o = 0.f;
#pragma unroll
        for (int k = 0; k < KNN; ++k)
            acc_o += wk[k] * aux[bk[k] * DAUX + lane];
        out[qidx * DAUX + lane] = acc_o / wsum;
    }
}

// ---------------------------------------------------------------------------
extern "C" void kernel_launch(void* const* d_in, const int* in_sizes, int n_in,
                              void* d_out, int out_size) {
    const float* q   = (const float*)d_in[0];   // embedding_features [4096,32]
    const float* db  = (const float*)d_in[1];   // db_embedding      [65536,32]
    const float* aux = (const float*)d_in[2];   // auxiliary_features[65536,32]
    float* out = (float*)d_out;                 // [4096,32]

    prep_kernel<<<NDB / 32, 256>>>(db);
    knn_kernel<<<NQ / QPB, THREADS>>>(q, aux, out);
}